// round 1
// baseline (speedup 1.0000x reference)
#include <cuda_runtime.h>

// Problem constants
#define B_ 128
#define T_ 500
#define M_ 512
#define L_ 128
#define NROWS (B_ * T_)   // 64000

typedef unsigned long long ull;

// ---------- packed f32x2 helpers (sm_103a: doubles fp32 FMA rate) ----------
__device__ __forceinline__ ull pack2(float lo, float hi) {
    ull r; asm("mov.b64 %0, {%1,%2};" : "=l"(r) : "f"(lo), "f"(hi)); return r;
}
__device__ __forceinline__ float2 unpack2(ull v) {
    float2 r; asm("mov.b64 {%0,%1}, %2;" : "=f"(r.x), "=f"(r.y) : "l"(v)); return r;
}
__device__ __forceinline__ void fma2(ull& d, ull a, ull b) {
    asm("fma.rn.f32x2 %0, %1, %2, %0;" : "+l"(d) : "l"(a), "l"(b));
}

__device__ __forceinline__ float sigm(float x) {
    return 1.0f / (1.0f + expf(-x));
}

// ============================================================================
// Kernel A: G = H @ [Wv | Wu]  (64000 x 512) @ (512 x 256), fused gate + Wa dot
// Block: 64 rows x 256 cols, 256 threads, per-thread 8 rows x 8 cols
// (cols per thread: v cols tc*4..tc*4+3 paired with u cols 128+tc*4..+3)
// Writes raw logits (the A_t output) to A_raw.
// ============================================================================
__global__ void __launch_bounds__(256) attn_gemm_kernel(
    const float* __restrict__ H,  const float* __restrict__ Wv,
    const float* __restrict__ bv, const float* __restrict__ Wu,
    const float* __restrict__ bu, const float* __restrict__ Wa,
    const float* __restrict__ ba, float* __restrict__ A_raw)
{
    __shared__ float Hs[64][20];      // 64 rows x 16 k, pad to 20 for alignment
    __shared__ float Ws[16][256];     // 16 k x (128 v | 128 u)
    __shared__ float WaS[L_], bvS[L_], buS[L_];

    const int tid = threadIdx.x;
    const int tr  = tid >> 5;         // warp id 0..7 -> row group (8 rows)
    const int tc  = tid & 31;         // lane -> col group (4 v cols + 4 u cols)
    const long n0 = (long)blockIdx.x * 64;

    if (tid < L_) { WaS[tid] = Wa[tid]; bvS[tid] = bv[tid]; buS[tid] = bu[tid]; }

    ull acc[8][4];                    // [row][0,1]=v pairs, [2,3]=u pairs
#pragma unroll
    for (int i = 0; i < 8; i++)
#pragma unroll
        for (int j = 0; j < 4; j++) acc[i][j] = 0ULL;

    const int lr = tid >> 2;              // H-tile load: row 0..63
    const int lk = (tid & 3) << 2;        // H-tile load: k offset {0,4,8,12}

    for (int kt = 0; kt < M_; kt += 16) {
        // stage global loads into registers
        float4 hv = *(const float4*)(H + (n0 + lr) * M_ + kt + lk);
        float4 wreg[4];
#pragma unroll
        for (int q = 0; q < 4; q++) {
            int idx = tid + q * 256;      // 0..1023 float4 slots (16 k x 64)
            int k = idx >> 6, c4 = idx & 63;
            const float* src = (c4 < 32) ? (Wv + (kt + k) * L_ + (c4 << 2))
                                         : (Wu + (kt + k) * L_ + ((c4 - 32) << 2));
            wreg[q] = *(const float4*)src;
        }
        __syncthreads();                  // previous tile fully consumed
        *(float4*)&Hs[lr][lk] = hv;
#pragma unroll
        for (int q = 0; q < 4; q++) {
            int idx = tid + q * 256;
            int k = idx >> 6, c4 = idx & 63;
            *(float4*)&Ws[k][c4 << 2] = wreg[q];
        }
        __syncthreads();

#pragma unroll
        for (int kk = 0; kk < 16; kk++) {
            float4 wv4 = *(const float4*)&Ws[kk][tc << 2];
            float4 wu4 = *(const float4*)&Ws[kk][128 + (tc << 2)];
            ull wv0 = pack2(wv4.x, wv4.y), wv1 = pack2(wv4.z, wv4.w);
            ull wu0 = pack2(wu4.x, wu4.y), wu1 = pack2(wu4.z, wu4.w);
#pragma unroll
            for (int i = 0; i < 8; i++) {
                float h = Hs[tr * 8 + i][kk];   // broadcast within warp
                ull h2 = pack2(h, h);
                fma2(acc[i][0], h2, wv0);
                fma2(acc[i][1], h2, wv1);
                fma2(acc[i][2], h2, wu0);
                fma2(acc[i][3], h2, wu1);
            }
        }
    }

    // Fused epilogue: gate + dot with Wa, warp-reduce per row, emit logits
    const float ba0 = __ldg(ba);
    const int c = tc << 2;
    float outv = 0.0f;
#pragma unroll
    for (int i = 0; i < 8; i++) {
        float2 v0 = unpack2(acc[i][0]);
        float2 v1 = unpack2(acc[i][1]);
        float2 u0 = unpack2(acc[i][2]);
        float2 u1 = unpack2(acc[i][3]);
        float p;
        p  = tanhf(v0.x + bvS[c + 0]) * sigm(u0.x + buS[c + 0]) * WaS[c + 0];
        p += tanhf(v0.y + bvS[c + 1]) * sigm(u0.y + buS[c + 1]) * WaS[c + 1];
        p += tanhf(v1.x + bvS[c + 2]) * sigm(u1.x + buS[c + 2]) * WaS[c + 2];
        p += tanhf(v1.y + bvS[c + 3]) * sigm(u1.y + buS[c + 3]) * WaS[c + 3];
#pragma unroll
        for (int o = 16; o; o >>= 1) p += __shfl_xor_sync(0xffffffffu, p, o);
        if (tc == i) outv = p;            // lane i keeps row i's sum
    }
    if (tc < 8) A_raw[n0 + tr * 8 + tc] = outv + ba0;
}

// ============================================================================
// Kernel B: per-bag softmax over T, weighted pooling of H, final [M]->[2] proj
// One block per bag, 512 threads (one per feature m).
// ============================================================================
__global__ void __launch_bounds__(512) pool_kernel(
    const float* __restrict__ H,  const float* __restrict__ Wc,
    const float* __restrict__ bc, const float* __restrict__ A_raw,
    float* __restrict__ A_sm, float* __restrict__ out)
{
    __shared__ float w[T_];
    __shared__ float redA[16], redB[16];
    __shared__ float sh_mx, sh_sum;

    const int tid  = threadIdx.x;
    const int b    = blockIdx.x;
    const int lane = tid & 31, wid = tid >> 5;   // 16 warps

    // ---- softmax over T=500 logits ----
    float a = (tid < T_) ? A_raw[b * T_ + tid] : -1e30f;
    float m = a;
#pragma unroll
    for (int o = 16; o; o >>= 1) m = fmaxf(m, __shfl_xor_sync(0xffffffffu, m, o));
    if (lane == 0) redA[wid] = m;
    __syncthreads();
    if (tid < 32) {
        float v = (tid < 16) ? redA[tid] : -1e30f;
#pragma unroll
        for (int o = 16; o; o >>= 1) v = fmaxf(v, __shfl_xor_sync(0xffffffffu, v, o));
        if (tid == 0) sh_mx = v;
    }
    __syncthreads();
    float e = (tid < T_) ? expf(a - sh_mx) : 0.0f;
    float s = e;
#pragma unroll
    for (int o = 16; o; o >>= 1) s += __shfl_xor_sync(0xffffffffu, s, o);
    if (lane == 0) redB[wid] = s;
    __syncthreads();
    if (tid < 32) {
        float v = (tid < 16) ? redB[tid] : 0.0f;
#pragma unroll
        for (int o = 16; o; o >>= 1) v += __shfl_xor_sync(0xffffffffu, v, o);
        if (tid == 0) sh_sum = v;
    }
    __syncthreads();
    if (tid < T_) {
        float wt = e / sh_sum;
        w[tid] = wt;
        A_sm[b * T_ + tid] = wt;
    }
    __syncthreads();

    // ---- weighted pooling: Mpool[m] = sum_t w[t] * H[b,t,m] ----
    float acc = 0.0f;
    const float* Hb = H + (size_t)b * T_ * M_ + tid;
#pragma unroll 10
    for (int t = 0; t < T_; t++)
        acc = fmaf(w[t], Hb[(size_t)t * M_], acc);

    // ---- out[b,:] = Mpool @ Wc + bc ----
    float c0 = acc * Wc[2 * tid];
    float c1 = acc * Wc[2 * tid + 1];
#pragma unroll
    for (int o = 16; o; o >>= 1) {
        c0 += __shfl_xor_sync(0xffffffffu, c0, o);
        c1 += __shfl_xor_sync(0xffffffffu, c1, o);
    }
    if (lane == 0) { redA[wid] = c0; redB[wid] = c1; }
    __syncthreads();
    if (tid == 0) {
        float r0 = 0.0f, r1 = 0.0f;
#pragma unroll
        for (int i = 0; i < 16; i++) { r0 += redA[i]; r1 += redB[i]; }
        out[b * 2 + 0] = r0 + bc[0];
        out[b * 2 + 1] = r1 + bc[1];
    }
}

// ============================================================================
// Launch: output layout is [out (B*2) | A_sm (B*T) | A_t raw logits (B*T)]
// ============================================================================
extern "C" void kernel_launch(void* const* d_in, const int* in_sizes, int n_in,
                              void* d_out, int out_size)
{
    const float* H  = (const float*)d_in[0];
    const float* Wv = (const float*)d_in[1];
    const float* bv = (const float*)d_in[2];
    const float* Wu = (const float*)d_in[3];
    const float* bu = (const float*)d_in[4];
    const float* Wa = (const float*)d_in[5];
    const float* ba = (const float*)d_in[6];
    const float* Wc = (const float*)d_in[7];
    const float* bc = (const float*)d_in[8];

    float* out   = (float*)d_out;            // [B,2]
    float* A_sm  = out + B_ * 2;             // [B,T]
    float* A_raw = A_sm + B_ * T_;           // [B,1,T] raw logits (A_t)

    attn_gemm_kernel<<<NROWS / 64, 256>>>(H, Wv, bv, Wu, bu, Wa, ba, A_raw);
    pool_kernel<<<B_, 512>>>(H, Wc, bc, A_raw, A_sm, out);
}

// round 3
// speedup vs baseline: 1.8318x; 1.8318x over previous
#include <cuda_runtime.h>
#include <cuda_bf16.h>
#include <cstdint>

typedef unsigned long long ull;

#define B_ 128
#define T_ 500
#define M_ 512
#define L_ 128
#define NROWS (B_ * T_)        // 64000

// ---- GEMM tiling ----
#define RM 64                  // rows per CTA
#define NC 256                 // interleaved (v,u) cols
#define KC 32                  // K per chunk
#define NCHUNK (M_ / KC)       // 16
#define ASTRIDE 80             // bytes per A row (64B data + 16 pad, /16 ok)
#define BSTRIDE 80

// per-stage smem layout (bytes)
#define A_HI 0
#define A_LO (RM * ASTRIDE)                      // 5120
#define B_HI (2 * RM * ASTRIDE)                  // 10240
#define B_LO (2 * RM * ASTRIDE + NC * BSTRIDE)   // 30720
#define STAGE (2 * RM * ASTRIDE + 2 * NC * BSTRIDE)  // 51200
#define DYN (2 * STAGE)        // 102400

// ---- persistent device scratch ----
__device__ __nv_bfloat16 g_Bhi[NC * M_];   // interleaved W^T hi [256][512]
__device__ __nv_bfloat16 g_Blo[NC * M_];
__device__ float g_part[B_ * 16 * M_];     // pooling partials (4 MB)

// ============================ helpers ============================
__device__ __forceinline__ uint32_t smem_u32(const void* p) {
    uint32_t a;
    asm("{ .reg .u64 t; cvta.to.shared.u64 t, %1; cvt.u32.u64 %0, t; }" : "=r"(a) : "l"(p));
    return a;
}
__device__ __forceinline__ float sigm(float x) { return 1.0f / (1.0f + expf(-x)); }

__device__ __forceinline__ void ldsm_x4(uint32_t (&r)[4], uint32_t addr) {
    asm volatile("ldmatrix.sync.aligned.m8n8.x4.shared.b16 {%0,%1,%2,%3}, [%4];"
                 : "=r"(r[0]), "=r"(r[1]), "=r"(r[2]), "=r"(r[3]) : "r"(addr));
}
__device__ __forceinline__ void ldsm_x2(uint32_t& r0, uint32_t& r1, uint32_t addr) {
    asm volatile("ldmatrix.sync.aligned.m8n8.x2.shared.b16 {%0,%1}, [%2];"
                 : "=r"(r0), "=r"(r1) : "r"(addr));
}
__device__ __forceinline__ void mma_bf16(float (&c)[4], const uint32_t (&a)[4],
                                         uint32_t b0, uint32_t b1) {
    asm volatile(
        "mma.sync.aligned.m16n8k16.row.col.f32.bf16.bf16.f32 "
        "{%0,%1,%2,%3}, {%4,%5,%6,%7}, {%8,%9}, {%0,%1,%2,%3};"
        : "+f"(c[0]), "+f"(c[1]), "+f"(c[2]), "+f"(c[3])
        : "r"(a[0]), "r"(a[1]), "r"(a[2]), "r"(a[3]), "r"(b0), "r"(b1));
}
__device__ __forceinline__ uint32_t pack2bf(__nv_bfloat16 a, __nv_bfloat16 b) {
    unsigned short ra = *(unsigned short*)&a, rb = *(unsigned short*)&b;
    return (uint32_t)ra | ((uint32_t)rb << 16);
}

// ============================================================================
// prep: interleaved W^T split into bf16 hi/lo.
//   col n = 2j   -> Wv[:, j]
//   col n = 2j+1 -> Wu[:, j]
// ============================================================================
__global__ void prep_kernel(const float* __restrict__ Wv, const float* __restrict__ Wu) {
    int n = blockIdx.x;        // 0..255
    int k = threadIdx.x;       // 0..511
    int j = n >> 1;
    float x = (n & 1) ? Wu[k * L_ + j] : Wv[k * L_ + j];
    __nv_bfloat16 hi = __float2bfloat16(x);
    __nv_bfloat16 lo = __float2bfloat16(x - __bfloat162float(hi));
    g_Bhi[n * M_ + k] = hi;
    g_Blo[n * M_ + k] = lo;
}

// ============================================================================
// GEMM (bf16x3 split via mma.sync) + fused gate/Wa epilogue -> logits A_raw
// grid = 1000, block = 256 (8 warps: 2 M x 4 N), CTA tile 64 x 256, K = 512
// ============================================================================
__global__ void __launch_bounds__(256, 2) gemm_attn_kernel(
    const float* __restrict__ H,  const float* __restrict__ bv,
    const float* __restrict__ bu, const float* __restrict__ Wa,
    const float* __restrict__ ba, float* __restrict__ A_raw)
{
    extern __shared__ char sm[];
    __shared__ float bvS[L_], buS[L_], WaS[L_];
    __shared__ float red[RM][4];

    const int tid  = threadIdx.x;
    const int lane = tid & 31;
    const int warp = tid >> 5;
    const int wm   = warp >> 2;      // 0..1
    const int wn   = warp & 3;       // 0..3
    const size_t n0 = (size_t)blockIdx.x * RM;

    if (tid < L_) { bvS[tid] = bv[tid]; buS[tid] = bu[tid]; WaS[tid] = Wa[tid]; }

    float acc[2][8][4];
#pragma unroll
    for (int mt = 0; mt < 2; mt++)
#pragma unroll
        for (int nt = 0; nt < 8; nt++)
#pragma unroll
            for (int i = 0; i < 4; i++) acc[mt][nt][i] = 0.0f;

    // staging registers for global loads
    float4 ar[2];
    uint4 bh[4], bl[4];

    const int a_row = tid >> 3;          // 0..31? (512 idx /8) -> handled per i
    (void)a_row;

    const uint32_t smb = smem_u32(sm);

    // precomputed per-thread LDSM addresses (within a stage, buf 0)
    // A: row = wm*32 + mt*16 + (lane&15); khalf = lane>>4
    const uint32_t a_ld_row = (uint32_t)(wm * 32 + (lane & 15));
    const uint32_t a_ld_koff = (uint32_t)((lane >> 4) * 16);
    // B: n = wn*64 + nt*8 + (lane&7); khalf = (lane>>3)&1
    const uint32_t b_ld_n = (uint32_t)(wn * 64 + (lane & 7));
    const uint32_t b_ld_koff = (uint32_t)(((lane >> 3) & 1) * 16);

#define LOADG(c)                                                                   \
    {                                                                              \
        const int kt = (c) * KC;                                                   \
        _Pragma("unroll")                                                          \
        for (int i = 0; i < 2; i++) {                                              \
            int idx = i * 256 + tid;                                               \
            int row = idx >> 3, f4 = idx & 7;                                      \
            ar[i] = *(const float4*)(H + (n0 + row) * M_ + kt + f4 * 4);           \
        }                                                                          \
        _Pragma("unroll")                                                          \
        for (int i = 0; i < 4; i++) {                                              \
            int idx = i * 256 + tid;                                               \
            int n = idx >> 2, k16 = idx & 3;                                       \
            size_t go = ((size_t)n * M_ + kt) * 2 + k16 * 16;                      \
            bh[i] = *(const uint4*)((const char*)g_Bhi + go);                      \
            bl[i] = *(const uint4*)((const char*)g_Blo + go);                      \
        }                                                                          \
    }

#define STORE(buf)                                                                 \
    {                                                                              \
        char* sb = sm + (buf) * STAGE;                                             \
        _Pragma("unroll")                                                          \
        for (int i = 0; i < 2; i++) {                                              \
            int idx = i * 256 + tid;                                               \
            int row = idx >> 3, f4 = idx & 7;                                      \
            float4 x = ar[i];                                                      \
            __nv_bfloat16 h0 = __float2bfloat16(x.x), h1 = __float2bfloat16(x.y);  \
            __nv_bfloat16 h2 = __float2bfloat16(x.z), h3 = __float2bfloat16(x.w);  \
            __nv_bfloat16 l0 = __float2bfloat16(x.x - __bfloat162float(h0));       \
            __nv_bfloat16 l1 = __float2bfloat16(x.y - __bfloat162float(h1));       \
            __nv_bfloat16 l2 = __float2bfloat16(x.z - __bfloat162float(h2));       \
            __nv_bfloat16 l3 = __float2bfloat16(x.w - __bfloat162float(h3));       \
            uint32_t off = (uint32_t)(row * ASTRIDE + f4 * 8);                     \
            *(uint2*)(sb + A_HI + off) = make_uint2(pack2bf(h0, h1), pack2bf(h2, h3)); \
            *(uint2*)(sb + A_LO + off) = make_uint2(pack2bf(l0, l1), pack2bf(l2, l3)); \
        }                                                                          \
        _Pragma("unroll")                                                          \
        for (int i = 0; i < 4; i++) {                                              \
            int idx = i * 256 + tid;                                               \
            int n = idx >> 2, k16 = idx & 3;                                       \
            uint32_t off = (uint32_t)(n * BSTRIDE + k16 * 16);                     \
            *(uint4*)(sb + B_HI + off) = bh[i];                                    \
            *(uint4*)(sb + B_LO + off) = bl[i];                                    \
        }                                                                          \
    }

#define COMPUTE(buf)                                                               \
    {                                                                              \
        const uint32_t sbase = smb + (buf) * STAGE;                                \
        _Pragma("unroll")                                                          \
        for (int ks = 0; ks < 2; ks++) {                                           \
            uint32_t ahh[2][4], ahl[2][4];                                         \
            _Pragma("unroll")                                                      \
            for (int mt = 0; mt < 2; mt++) {                                       \
                uint32_t aoff = (a_ld_row + mt * 16) * ASTRIDE + ks * 32 + a_ld_koff; \
                ldsm_x4(ahh[mt], sbase + A_HI + aoff);                             \
                ldsm_x4(ahl[mt], sbase + A_LO + aoff);                             \
            }                                                                      \
            _Pragma("unroll")                                                      \
            for (int nt = 0; nt < 8; nt++) {                                       \
                uint32_t boff = (b_ld_n + nt * 8) * BSTRIDE + ks * 32 + b_ld_koff; \
                uint32_t bh0, bh1, bl0, bl1;                                       \
                ldsm_x2(bh0, bh1, sbase + B_HI + boff);                            \
                ldsm_x2(bl0, bl1, sbase + B_LO + boff);                            \
                _Pragma("unroll")                                                  \
                for (int mt = 0; mt < 2; mt++) {                                   \
                    mma_bf16(acc[mt][nt], ahh[mt], bh0, bh1);                      \
                    mma_bf16(acc[mt][nt], ahh[mt], bl0, bl1);                      \
                    mma_bf16(acc[mt][nt], ahl[mt], bh0, bh1);                      \
                }                                                                  \
            }                                                                      \
        }                                                                          \
    }

    // ---- pipelined main loop ----
    LOADG(0);
    STORE(0);
    __syncthreads();
#pragma unroll 1
    for (int c = 0; c < NCHUNK; c++) {
        if (c + 1 < NCHUNK) LOADG(c + 1);
        COMPUTE(c & 1);
        if (c + 1 < NCHUNK) STORE((c + 1) & 1);
        __syncthreads();
    }

    // ---- fused epilogue: gate + Wa dot, in-thread (v,u) pairs ----
#pragma unroll
    for (int mt = 0; mt < 2; mt++) {
        float p0 = 0.0f, p1 = 0.0f;
#pragma unroll
        for (int nt = 0; nt < 8; nt++) {
            int j = wn * 32 + nt * 4 + (lane & 3);
            float bvj = bvS[j], buj = buS[j], waj = WaS[j];
            p0 += tanhf(acc[mt][nt][0] + bvj) * sigm(acc[mt][nt][1] + buj) * waj;
            p1 += tanhf(acc[mt][nt][2] + bvj) * sigm(acc[mt][nt][3] + buj) * waj;
        }
        p0 += __shfl_xor_sync(~0u, p0, 1); p0 += __shfl_xor_sync(~0u, p0, 2);
        p1 += __shfl_xor_sync(~0u, p1, 1); p1 += __shfl_xor_sync(~0u, p1, 2);
        if ((lane & 3) == 0) {
            int r = wm * 32 + mt * 16 + (lane >> 2);
            red[r][wn] = p0;
            red[r + 8][wn] = p1;
        }
    }
    __syncthreads();
    if (tid < RM) {
        float s = red[tid][0] + red[tid][1] + red[tid][2] + red[tid][3] + __ldg(ba);
        A_raw[n0 + tid] = s;
    }
}

// ============================================================================
// pool1: per (bag, quarter) — softmax (redundant x4) + float4 partial pooling
// 512 threads: 4 t-rows in flight x 128 float4 lanes
// ============================================================================
__global__ void __launch_bounds__(512) pool1_kernel(
    const float* __restrict__ H, const float* __restrict__ A_raw,
    float* __restrict__ A_sm)
{
    __shared__ float w[T_];
    __shared__ float red[16];
    __shared__ float sh_mx, sh_sum;

    const int tid = threadIdx.x;
    const int b = blockIdx.x >> 2;
    const int q = blockIdx.x & 3;
    const int lane = tid & 31, wid = tid >> 5;

    float a = (tid < T_) ? A_raw[b * T_ + tid] : -1e30f;
    float m = a;
#pragma unroll
    for (int o = 16; o; o >>= 1) m = fmaxf(m, __shfl_xor_sync(~0u, m, o));
    if (lane == 0) red[wid] = m;
    __syncthreads();
    if (tid < 32) {
        float v = (tid < 16) ? red[tid] : -1e30f;
#pragma unroll
        for (int o = 16; o; o >>= 1) v = fmaxf(v, __shfl_xor_sync(~0u, v, o));
        if (tid == 0) sh_mx = v;
    }
    __syncthreads();
    float e = (tid < T_) ? expf(a - sh_mx) : 0.0f;
    float s = e;
#pragma unroll
    for (int o = 16; o; o >>= 1) s += __shfl_xor_sync(~0u, s, o);
    __syncthreads();
    if (lane == 0) red[wid] = s;
    __syncthreads();
    if (tid < 32) {
        float v = (tid < 16) ? red[tid] : 0.0f;
#pragma unroll
        for (int o = 16; o; o >>= 1) v += __shfl_xor_sync(~0u, v, o);
        if (tid == 0) sh_sum = v;
    }
    __syncthreads();
    if (tid < T_) {
        float wt = e / sh_sum;
        w[tid] = wt;
        if (q == 0) A_sm[b * T_ + tid] = wt;
    }
    __syncthreads();

    // partial pooling: 4 t-rows in flight, float4 per thread
    const int g  = tid >> 7;     // 0..3 row-group
    const int m4 = tid & 127;    // float4 lane
    const int t0 = q * 125;
    float4 acc = make_float4(0.f, 0.f, 0.f, 0.f);
#pragma unroll 4
    for (int t = t0 + g; t < t0 + 125; t += 4) {
        float4 h = *(const float4*)(H + ((size_t)b * T_ + t) * M_ + m4 * 4);
        float wt = w[t];
        acc.x = fmaf(wt, h.x, acc.x);
        acc.y = fmaf(wt, h.y, acc.y);
        acc.z = fmaf(wt, h.z, acc.z);
        acc.w = fmaf(wt, h.w, acc.w);
    }
    *(float4*)(g_part + ((size_t)(b * 16 + q * 4 + g)) * M_ + m4 * 4) = acc;
}

// ============================================================================
// pool2: combine 16 partials per bag, project M->2
// ============================================================================
__global__ void __launch_bounds__(512) pool2_kernel(
    const float* __restrict__ Wc, const float* __restrict__ bc,
    float* __restrict__ out)
{
    __shared__ float redA[16], redB[16];
    const int tid = threadIdx.x;
    const int b = blockIdx.x;
    const int lane = tid & 31, wid = tid >> 5;

    float mpool = 0.0f;
#pragma unroll
    for (int p = 0; p < 16; p++)
        mpool += g_part[((size_t)(b * 16 + p)) * M_ + tid];

    float c0 = mpool * Wc[2 * tid];
    float c1 = mpool * Wc[2 * tid + 1];
#pragma unroll
    for (int o = 16; o; o >>= 1) {
        c0 += __shfl_xor_sync(~0u, c0, o);
        c1 += __shfl_xor_sync(~0u, c1, o);
    }
    if (lane == 0) { redA[wid] = c0; redB[wid] = c1; }
    __syncthreads();
    if (tid == 0) {
        float r0 = 0.0f, r1 = 0.0f;
#pragma unroll
        for (int i = 0; i < 16; i++) { r0 += redA[i]; r1 += redB[i]; }
        out[b * 2 + 0] = r0 + bc[0];
        out[b * 2 + 1] = r1 + bc[1];
    }
}

// ============================================================================
// Launch. Output layout: [out (B*2) | A_sm (B*T) | A_t raw logits (B*T)]
// ============================================================================
extern "C" void kernel_launch(void* const* d_in, const int* in_sizes, int n_in,
                              void* d_out, int out_size)
{
    const float* H  = (const float*)d_in[0];
    const float* Wv = (const float*)d_in[1];
    const float* bv = (const float*)d_in[2];
    const float* Wu = (const float*)d_in[3];
    const float* bu = (const float*)d_in[4];
    const float* Wa = (const float*)d_in[5];
    const float* ba = (const float*)d_in[6];
    const float* Wc = (const float*)d_in[7];
    const float* bc = (const float*)d_in[8];

    float* out   = (float*)d_out;
    float* A_sm  = out + B_ * 2;
    float* A_raw = A_sm + B_ * T_;

    cudaFuncSetAttribute(gemm_attn_kernel,
                         cudaFuncAttributeMaxDynamicSharedMemorySize, DYN);

    prep_kernel<<<NC, M_>>>(Wv, Wu);
    gemm_attn_kernel<<<NROWS / RM, 256, DYN>>>(H, bv, bu, Wa, ba, A_raw);
    pool1_kernel<<<B_ * 4, 512>>>(H, A_raw, A_sm);
    pool2_kernel<<<B_, 512>>>(Wc, bc, out);
}

// round 4
// speedup vs baseline: 3.9575x; 2.1605x over previous
#include <cuda_runtime.h>
#include <cuda_fp16.h>
#include <cstdint>

#define B_ 128
#define T_ 500
#define M_ 512
#define L_ 128
#define NROWS (B_ * T_)        // 64000

// ---- GEMM tiling ----
#define RM 64                  // rows per CTA
#define NC 256                 // interleaved (v,u) cols
#define KC 32                  // K per chunk
#define NCHUNK (M_ / KC)       // 16
#define ASTRIDE 80             // bytes per A row (64B data + 16 pad)
#define BSTRIDE 80

// per-stage smem layout (bytes)
#define A_HI 0
#define A_LO (RM * ASTRIDE)            // 5120
#define B_OFF (2 * RM * ASTRIDE)       // 10240
#define STAGE (B_OFF + NC * BSTRIDE)   // 30720
#define DYN (2 * STAGE)                // 61440

// ---- persistent device scratch ----
__device__ __half g_Bh[NC * M_];   // interleaved W^T fp16 [256][512]
__device__ float  g_C[NROWS * 2];  // C = H @ Wc  [64000][2]

// ============================ helpers ============================
__device__ __forceinline__ uint32_t smem_u32(const void* p) {
    uint32_t a;
    asm("{ .reg .u64 t; cvta.to.shared.u64 t, %1; cvt.u32.u64 %0, t; }" : "=r"(a) : "l"(p));
    return a;
}
__device__ __forceinline__ float sigm(float x) { return 1.0f / (1.0f + expf(-x)); }

__device__ __forceinline__ void ldsm_x4(uint32_t (&r)[4], uint32_t addr) {
    asm volatile("ldmatrix.sync.aligned.m8n8.x4.shared.b16 {%0,%1,%2,%3}, [%4];"
                 : "=r"(r[0]), "=r"(r[1]), "=r"(r[2]), "=r"(r[3]) : "r"(addr));
}
__device__ __forceinline__ void mma_f16(float (&c)[4], const uint32_t (&a)[4],
                                        uint32_t b0, uint32_t b1) {
    asm volatile(
        "mma.sync.aligned.m16n8k16.row.col.f32.f16.f16.f32 "
        "{%0,%1,%2,%3}, {%4,%5,%6,%7}, {%8,%9}, {%0,%1,%2,%3};"
        : "+f"(c[0]), "+f"(c[1]), "+f"(c[2]), "+f"(c[3])
        : "r"(a[0]), "r"(a[1]), "r"(a[2]), "r"(a[3]), "r"(b0), "r"(b1));
}
__device__ __forceinline__ uint32_t pack2h(__half a, __half b) {
    unsigned short ra = *(unsigned short*)&a, rb = *(unsigned short*)&b;
    return (uint32_t)ra | ((uint32_t)rb << 16);
}
__device__ __forceinline__ void cpasync16(uint32_t dst, const void* src) {
    asm volatile("cp.async.cg.shared.global [%0], [%1], 16;" :: "r"(dst), "l"(src));
}
#define CP_COMMIT() asm volatile("cp.async.commit_group;" ::: "memory")
#define CP_WAIT0()  asm volatile("cp.async.wait_group 0;" ::: "memory")

// ============================================================================
// prep: interleaved W^T to fp16.  col 2j -> Wv[:,j], col 2j+1 -> Wu[:,j]
// ============================================================================
__global__ void prep_kernel(const float* __restrict__ Wv, const float* __restrict__ Wu) {
    int n = blockIdx.x;        // 0..255
    int k = threadIdx.x;       // 0..511
    int j = n >> 1;
    float x = (n & 1) ? Wu[k * L_ + j] : Wv[k * L_ + j];
    g_Bh[n * M_ + k] = __float2half_rn(x);
}

// ============================================================================
// GEMM (fp16 A-split x2 via mma.sync) + fused gate/Wa epilogue + fused C=H@Wc
// grid = 1000, block = 256 (8 warps: 2 M x 4 N), CTA tile 64 x 256, K = 512
// ============================================================================
__global__ void __launch_bounds__(256, 2) gemm_attn_kernel(
    const float* __restrict__ H,  const float* __restrict__ bv,
    const float* __restrict__ bu, const float* __restrict__ Wa,
    const float* __restrict__ ba, const float* __restrict__ Wc,
    float* __restrict__ A_raw)
{
    extern __shared__ char sm[];
    __shared__ float bvS[L_], buS[L_], WaS[L_];
    __shared__ float Wc0S[M_], Wc1S[M_];
    __shared__ float red[RM][4];

    const int tid  = threadIdx.x;
    const int lane = tid & 31;
    const int warp = tid >> 5;
    const int wm   = warp >> 2;      // 0..1
    const int wn   = warp & 3;       // 0..3
    const size_t n0 = (size_t)blockIdx.x * RM;

    if (tid < L_) { bvS[tid] = bv[tid]; buS[tid] = bu[tid]; WaS[tid] = Wa[tid]; }
    if (tid < M_ - 256) { }  // (all 512 Wc rows loaded below by 256 threads x2)
#pragma unroll
    for (int i = 0; i < 2; i++) {
        int k = i * 256 + tid;
        Wc0S[k] = Wc[2 * k];
        Wc1S[k] = Wc[2 * k + 1];
    }

    float acc[2][8][4];
#pragma unroll
    for (int mt = 0; mt < 2; mt++)
#pragma unroll
        for (int nt = 0; nt < 8; nt++)
#pragma unroll
            for (int i = 0; i < 4; i++) acc[mt][nt][i] = 0.0f;

    float4 ar[2];                    // A staging regs
    float cc0 = 0.0f, cc1 = 0.0f;    // fused C = H @ Wc accumulators

    const uint32_t smb = smem_u32(sm);

    // LDSM per-thread offsets (within a stage)
    const uint32_t a_ld_row  = (uint32_t)(wm * 32 + (lane & 15));
    const uint32_t a_ld_koff = (uint32_t)((lane >> 4) * 16);
    // B x4: lanes 0-7: n..n+7 k0 | 8-15: k1 | 16-23: n+8.. k0 | 24-31: k1
    const uint32_t b_ld_n    = (uint32_t)(wn * 64 + (lane & 7) + ((lane >> 4) << 3));
    const uint32_t b_ld_koff = (uint32_t)(((lane >> 3) & 1) * 16);

    // C-accum thread mapping: 4 threads per row
    const int cr = tid >> 2, csub = tid & 3;

#define LOADG_A(c)                                                                 \
    {                                                                              \
        const int kt = (c) * KC;                                                   \
        _Pragma("unroll")                                                          \
        for (int i = 0; i < 2; i++) {                                              \
            int idx = i * 256 + tid;                                               \
            int row = idx >> 3, f4 = idx & 7;                                      \
            ar[i] = *(const float4*)(H + (n0 + row) * M_ + kt + f4 * 4);           \
        }                                                                          \
    }

#define CPASYNC_B(c, buf)                                                          \
    {                                                                              \
        const int kt = (c) * KC;                                                   \
        const uint32_t db = smb + (buf) * STAGE + B_OFF;                           \
        _Pragma("unroll")                                                          \
        for (int i = 0; i < 4; i++) {                                              \
            int idx = i * 256 + tid;                                               \
            int n = idx >> 2, k16 = idx & 3;                                       \
            cpasync16(db + n * BSTRIDE + k16 * 16, g_Bh + n * M_ + kt + k16 * 8);  \
        }                                                                          \
        CP_COMMIT();                                                               \
    }

#define STORE_A(buf)                                                               \
    {                                                                              \
        char* sb = sm + (buf) * STAGE;                                             \
        _Pragma("unroll")                                                          \
        for (int i = 0; i < 2; i++) {                                              \
            int idx = i * 256 + tid;                                               \
            int row = idx >> 3, f4 = idx & 7;                                      \
            float4 x = ar[i];                                                      \
            __half h0 = __float2half_rn(x.x), h1 = __float2half_rn(x.y);           \
            __half h2 = __float2half_rn(x.z), h3 = __float2half_rn(x.w);           \
            __half l0 = __float2half_rn(x.x - __half2float(h0));                   \
            __half l1 = __float2half_rn(x.y - __half2float(h1));                   \
            __half l2 = __float2half_rn(x.z - __half2float(h2));                   \
            __half l3 = __float2half_rn(x.w - __half2float(h3));                   \
            uint32_t off = (uint32_t)(row * ASTRIDE + f4 * 8);                     \
            *(uint2*)(sb + A_HI + off) = make_uint2(pack2h(h0, h1), pack2h(h2, h3)); \
            *(uint2*)(sb + A_LO + off) = make_uint2(pack2h(l0, l1), pack2h(l2, l3)); \
        }                                                                          \
    }

#define COMPUTE(buf)                                                               \
    {                                                                              \
        const uint32_t sbase = smb + (buf) * STAGE;                                \
        _Pragma("unroll")                                                          \
        for (int ks = 0; ks < 2; ks++) {                                           \
            uint32_t ahh[2][4], ahl[2][4];                                         \
            _Pragma("unroll")                                                      \
            for (int mt = 0; mt < 2; mt++) {                                       \
                uint32_t aoff = (a_ld_row + mt * 16) * ASTRIDE + ks * 32 + a_ld_koff; \
                ldsm_x4(ahh[mt], sbase + A_HI + aoff);                             \
                ldsm_x4(ahl[mt], sbase + A_LO + aoff);                             \
            }                                                                      \
            _Pragma("unroll")                                                      \
            for (int p = 0; p < 4; p++) {                                          \
                uint32_t br[4];                                                    \
                uint32_t boff = (b_ld_n + p * 16) * BSTRIDE + ks * 32 + b_ld_koff; \
                ldsm_x4(br, sbase + B_OFF + boff);                                 \
                _Pragma("unroll")                                                  \
                for (int mt = 0; mt < 2; mt++) {                                   \
                    mma_f16(acc[mt][2 * p],     ahh[mt], br[0], br[1]);            \
                    mma_f16(acc[mt][2 * p],     ahl[mt], br[0], br[1]);            \
                    mma_f16(acc[mt][2 * p + 1], ahh[mt], br[2], br[3]);            \
                    mma_f16(acc[mt][2 * p + 1], ahl[mt], br[2], br[3]);            \
                }                                                                  \
            }                                                                      \
        }                                                                          \
    }

#define C_ACCUM(c, buf)                                                            \
    {                                                                              \
        const char* sb = sm + (buf) * STAGE;                                       \
        uint4 hh = *(const uint4*)(sb + A_HI + cr * ASTRIDE + csub * 16);          \
        uint4 ll = *(const uint4*)(sb + A_LO + cr * ASTRIDE + csub * 16);          \
        const __half2* h2 = (const __half2*)&hh;                                   \
        const __half2* l2 = (const __half2*)&ll;                                   \
        const int kb = (c) * KC + csub * 8;                                        \
        _Pragma("unroll")                                                          \
        for (int j = 0; j < 4; j++) {                                              \
            float2 a = __half22float2(h2[j]);                                      \
            float2 b = __half22float2(l2[j]);                                      \
            float f0 = a.x + b.x, f1 = a.y + b.y;                                  \
            cc0 = fmaf(f0, Wc0S[kb + 2 * j], cc0);                                 \
            cc0 = fmaf(f1, Wc0S[kb + 2 * j + 1], cc0);                             \
            cc1 = fmaf(f0, Wc1S[kb + 2 * j], cc1);                                 \
            cc1 = fmaf(f1, Wc1S[kb + 2 * j + 1], cc1);                             \
        }                                                                          \
    }

    // ---- pipelined main loop ----
    CPASYNC_B(0, 0);
    LOADG_A(0);
    STORE_A(0);
    CP_WAIT0();
    __syncthreads();
#pragma unroll 1
    for (int c = 0; c < NCHUNK; c++) {
        const int buf = c & 1;
        if (c + 1 < NCHUNK) {
            CPASYNC_B(c + 1, buf ^ 1);
            LOADG_A(c + 1);
        }
        COMPUTE(buf);
        C_ACCUM(c, buf);
        if (c + 1 < NCHUNK) {
            STORE_A(buf ^ 1);
            CP_WAIT0();
        }
        __syncthreads();
    }

    // ---- C = H@Wc reduce + store (4 threads/row -> lane group of 4) ----
    cc0 += __shfl_xor_sync(~0u, cc0, 1); cc0 += __shfl_xor_sync(~0u, cc0, 2);
    cc1 += __shfl_xor_sync(~0u, cc1, 1); cc1 += __shfl_xor_sync(~0u, cc1, 2);
    if (csub == 0) {
        g_C[(n0 + cr) * 2 + 0] = cc0;
        g_C[(n0 + cr) * 2 + 1] = cc1;
    }

    // ---- fused epilogue: gate + Wa dot, in-thread (v,u) pairs ----
#pragma unroll
    for (int mt = 0; mt < 2; mt++) {
        float p0 = 0.0f, p1 = 0.0f;
#pragma unroll
        for (int nt = 0; nt < 8; nt++) {
            int j = wn * 32 + nt * 4 + (lane & 3);
            float bvj = bvS[j], buj = buS[j], waj = WaS[j];
            p0 += tanhf(acc[mt][nt][0] + bvj) * sigm(acc[mt][nt][1] + buj) * waj;
            p1 += tanhf(acc[mt][nt][2] + bvj) * sigm(acc[mt][nt][3] + buj) * waj;
        }
        p0 += __shfl_xor_sync(~0u, p0, 1); p0 += __shfl_xor_sync(~0u, p0, 2);
        p1 += __shfl_xor_sync(~0u, p1, 1); p1 += __shfl_xor_sync(~0u, p1, 2);
        if ((lane & 3) == 0) {
            int r = wm * 32 + mt * 16 + (lane >> 2);
            red[r][wn] = p0;
            red[r + 8][wn] = p1;
        }
    }
    __syncthreads();
    if (tid < RM) {
        float s = red[tid][0] + red[tid][1] + red[tid][2] + red[tid][3] + __ldg(ba);
        A_raw[n0 + tid] = s;
    }
}

// ============================================================================
// pool: per bag — softmax over T, then out[b] = sum_t w[t] * C[t]  (+bc)
// grid = 128, block = 512
// ============================================================================
__global__ void __launch_bounds__(512) pool_kernel(
    const float* __restrict__ A_raw, const float* __restrict__ bc,
    float* __restrict__ A_sm, float* __restrict__ out)
{
    __shared__ float red[16], redB[16];
    __shared__ float sh_mx, sh_sum;

    const int tid = threadIdx.x;
    const int b = blockIdx.x;
    const int lane = tid & 31, wid = tid >> 5;

    float a = (tid < T_) ? A_raw[b * T_ + tid] : -1e30f;
    float m = a;
#pragma unroll
    for (int o = 16; o; o >>= 1) m = fmaxf(m, __shfl_xor_sync(~0u, m, o));
    if (lane == 0) red[wid] = m;
    __syncthreads();
    if (tid < 32) {
        float v = (tid < 16) ? red[tid] : -1e30f;
#pragma unroll
        for (int o = 16; o; o >>= 1) v = fmaxf(v, __shfl_xor_sync(~0u, v, o));
        if (tid == 0) sh_mx = v;
    }
    __syncthreads();
    float e = (tid < T_) ? expf(a - sh_mx) : 0.0f;
    float s = e;
#pragma unroll
    for (int o = 16; o; o >>= 1) s += __shfl_xor_sync(~0u, s, o);
    __syncthreads();
    if (lane == 0) red[wid] = s;
    __syncthreads();
    if (tid < 32) {
        float v = (tid < 16) ? red[tid] : 0.0f;
#pragma unroll
        for (int o = 16; o; o >>= 1) v += __shfl_xor_sync(~0u, v, o);
        if (tid == 0) sh_sum = v;
    }
    __syncthreads();

    float wt = 0.0f;
    if (tid < T_) {
        wt = e / sh_sum;
        A_sm[b * T_ + tid] = wt;
    }

    // out[b] = sum_t wt * C[t]
    float c0 = 0.0f, c1 = 0.0f;
    if (tid < T_) {
        float2 cv = *(const float2*)(g_C + (b * T_ + tid) * 2);
        c0 = wt * cv.x;
        c1 = wt * cv.y;
    }
#pragma unroll
    for (int o = 16; o; o >>= 1) {
        c0 += __shfl_xor_sync(~0u, c0, o);
        c1 += __shfl_xor_sync(~0u, c1, o);
    }
    __syncthreads();
    if (lane == 0) { red[wid] = c0; redB[wid] = c1; }
    __syncthreads();
    if (tid == 0) {
        float r0 = 0.0f, r1 = 0.0f;
#pragma unroll
        for (int i = 0; i < 16; i++) { r0 += red[i]; r1 += redB[i]; }
        out[b * 2 + 0] = r0 + bc[0];
        out[b * 2 + 1] = r1 + bc[1];
    }
}

// ============================================================================
// Launch. Output layout: [out (B*2) | A_sm (B*T) | A_t raw logits (B*T)]
// ============================================================================
extern "C" void kernel_launch(void* const* d_in, const int* in_sizes, int n_in,
                              void* d_out, int out_size)
{
    const float* H  = (const float*)d_in[0];
    const float* Wv = (const float*)d_in[1];
    const float* bv = (const float*)d_in[2];
    const float* Wu = (const float*)d_in[3];
    const float* bu = (const float*)d_in[4];
    const float* Wa = (const float*)d_in[5];
    const float* ba = (const float*)d_in[6];
    const float* Wc = (const float*)d_in[7];
    const float* bc = (const float*)d_in[8];

    float* out   = (float*)d_out;
    float* A_sm  = out + B_ * 2;
    float* A_raw = A_sm + B_ * T_;

    cudaFuncSetAttribute(gemm_attn_kernel,
                         cudaFuncAttributeMaxDynamicSharedMemorySize, DYN);

    prep_kernel<<<NC, M_>>>(Wv, Wu);
    gemm_attn_kernel<<<NROWS / RM, 256, DYN>>>(H, bv, bu, Wa, ba, Wc, A_raw);
    pool_kernel<<<B_, 512>>>(A_raw, bc, A_sm, out);
}

// round 5
// speedup vs baseline: 5.5071x; 1.3916x over previous
#include <cuda_runtime.h>
#include <cuda_fp16.h>
#include <cstdint>

#define B_ 128
#define T_ 500
#define M_ 512
#define L_ 128
#define NROWS (B_ * T_)        // 64000

// ---- GEMM tiling ----
#define RM 64                  // rows per CTA
#define NC 256                 // interleaved (v,u) cols
#define KC 64                  // K per chunk
#define NCHUNK (M_ / KC)       // 8
#define ASTRIDE 144            // bytes per A row (128B data + 16 pad)
#define BSTRIDE 144

// per-stage smem layout (bytes)
#define A_HI 0
#define B_OFF (RM * ASTRIDE)             // 9216
#define STAGE (B_OFF + NC * BSTRIDE)     // 46080
#define DYN (2 * STAGE)                  // 92160

// ---- persistent device scratch ----
__device__ __half g_Bh[NC * M_];   // interleaved W^T fp16 [256][512]
__device__ float  g_C[NROWS * 2];  // C = H @ Wc  [64000][2]

// ============================ helpers ============================
__device__ __forceinline__ uint32_t smem_u32(const void* p) {
    uint32_t a;
    asm("{ .reg .u64 t; cvta.to.shared.u64 t, %1; cvt.u32.u64 %0, t; }" : "=r"(a) : "l"(p));
    return a;
}
__device__ __forceinline__ float sigm(float x) { return 1.0f / (1.0f + expf(-x)); }

__device__ __forceinline__ void ldsm_x4(uint32_t (&r)[4], uint32_t addr) {
    asm volatile("ldmatrix.sync.aligned.m8n8.x4.shared.b16 {%0,%1,%2,%3}, [%4];"
                 : "=r"(r[0]), "=r"(r[1]), "=r"(r[2]), "=r"(r[3]) : "r"(addr));
}
__device__ __forceinline__ void mma_f16(float (&c)[4], const uint32_t (&a)[4],
                                        uint32_t b0, uint32_t b1) {
    asm volatile(
        "mma.sync.aligned.m16n8k16.row.col.f32.f16.f16.f32 "
        "{%0,%1,%2,%3}, {%4,%5,%6,%7}, {%8,%9}, {%0,%1,%2,%3};"
        : "+f"(c[0]), "+f"(c[1]), "+f"(c[2]), "+f"(c[3])
        : "r"(a[0]), "r"(a[1]), "r"(a[2]), "r"(a[3]), "r"(b0), "r"(b1));
}
__device__ __forceinline__ uint32_t pack2h(__half a, __half b) {
    unsigned short ra = *(unsigned short*)&a, rb = *(unsigned short*)&b;
    return (uint32_t)ra | ((uint32_t)rb << 16);
}
__device__ __forceinline__ void cpasync16(uint32_t dst, const void* src) {
    asm volatile("cp.async.cg.shared.global [%0], [%1], 16;" :: "r"(dst), "l"(src));
}
#define CP_COMMIT() asm volatile("cp.async.commit_group;" ::: "memory")
#define CP_WAIT0()  asm volatile("cp.async.wait_group 0;" ::: "memory")

// ============================================================================
// prep: interleaved W^T to fp16.  col 2j -> Wv[:,j], col 2j+1 -> Wu[:,j]
// ============================================================================
__global__ void prep_kernel(const float* __restrict__ Wv, const float* __restrict__ Wu) {
    int n = blockIdx.x;        // 0..255
    int k = threadIdx.x;       // 0..511
    int j = n >> 1;
    float x = (n & 1) ? Wu[k * L_ + j] : Wv[k * L_ + j];
    g_Bh[n * M_ + k] = __float2half_rn(x);
}

// ============================================================================
// GEMM (fp16 x fp16 via mma.sync) + fused gate/Wa epilogue + fp32 C=H@Wc
// grid = 1000, block = 256 (8 warps: 2 M x 4 N), CTA tile 64 x 256, K = 512
// ============================================================================
__global__ void __launch_bounds__(256, 2) gemm_attn_kernel(
    const float* __restrict__ H,  const float* __restrict__ bv,
    const float* __restrict__ bu, const float* __restrict__ Wa,
    const float* __restrict__ ba, const float* __restrict__ Wc,
    float* __restrict__ A_raw)
{
    extern __shared__ char sm[];
    __shared__ float bvS[L_], buS[L_], WaS[L_];
    __shared__ float Wc0S[M_], Wc1S[M_];
    __shared__ float red[RM][4];

    const int tid  = threadIdx.x;
    const int lane = tid & 31;
    const int warp = tid >> 5;
    const int wm   = warp >> 2;      // 0..1
    const int wn   = warp & 3;       // 0..3
    const size_t n0 = (size_t)blockIdx.x * RM;

    if (tid < L_) { bvS[tid] = bv[tid]; buS[tid] = bu[tid]; WaS[tid] = Wa[tid]; }
#pragma unroll
    for (int i = 0; i < 2; i++) {
        int k = i * 256 + tid;
        Wc0S[k] = Wc[2 * k];
        Wc1S[k] = Wc[2 * k + 1];
    }

    float acc[2][8][4];
#pragma unroll
    for (int mt = 0; mt < 2; mt++)
#pragma unroll
        for (int nt = 0; nt < 8; nt++)
#pragma unroll
            for (int i = 0; i < 4; i++) acc[mt][nt][i] = 0.0f;

    float4 ar[4];                    // A staging regs (fp32, also feeds C)
    float cc[4][2];                  // fp32 C = H @ Wc accumulators (4 rows)
#pragma unroll
    for (int i = 0; i < 4; i++) { cc[i][0] = 0.0f; cc[i][1] = 0.0f; }

    const uint32_t smb = smem_u32(sm);

    // LDSM per-thread offsets (within a stage)
    const uint32_t a_ld_row  = (uint32_t)(wm * 32 + (lane & 15));
    const uint32_t a_ld_koff = (uint32_t)((lane >> 4) * 16);
    const uint32_t b_ld_n    = (uint32_t)(wn * 64 + (lane & 7) + ((lane >> 4) << 3));
    const uint32_t b_ld_koff = (uint32_t)(((lane >> 3) & 1) * 16);

    // C-accum mapping: thread covers rows (tid>>4)+16i, k-slice f4*4..+3
    const int c_f4 = tid & 15;

#define LOADG_A(c)                                                                 \
    {                                                                              \
        const int kt = (c) * KC;                                                   \
        _Pragma("unroll")                                                          \
        for (int i = 0; i < 4; i++) {                                              \
            int idx = i * 256 + tid;                                               \
            int row = idx >> 4, f4 = idx & 15;                                     \
            ar[i] = *(const float4*)(H + (n0 + row) * M_ + kt + f4 * 4);           \
        }                                                                          \
    }

#define C_ACCUM(c)                                                                 \
    {                                                                              \
        const int kb = (c) * KC + c_f4 * 4;                                        \
        float w00 = Wc0S[kb], w01 = Wc0S[kb + 1], w02 = Wc0S[kb + 2], w03 = Wc0S[kb + 3]; \
        float w10 = Wc1S[kb], w11 = Wc1S[kb + 1], w12 = Wc1S[kb + 2], w13 = Wc1S[kb + 3]; \
        _Pragma("unroll")                                                          \
        for (int i = 0; i < 4; i++) {                                              \
            cc[i][0] = fmaf(ar[i].x, w00, cc[i][0]);                               \
            cc[i][0] = fmaf(ar[i].y, w01, cc[i][0]);                               \
            cc[i][0] = fmaf(ar[i].z, w02, cc[i][0]);                               \
            cc[i][0] = fmaf(ar[i].w, w03, cc[i][0]);                               \
            cc[i][1] = fmaf(ar[i].x, w10, cc[i][1]);                               \
            cc[i][1] = fmaf(ar[i].y, w11, cc[i][1]);                               \
            cc[i][1] = fmaf(ar[i].z, w12, cc[i][1]);                               \
            cc[i][1] = fmaf(ar[i].w, w13, cc[i][1]);                               \
        }                                                                          \
    }

#define CPASYNC_B(c, buf)                                                          \
    {                                                                              \
        const int kt = (c) * KC;                                                   \
        const uint32_t db = smb + (buf) * STAGE + B_OFF;                           \
        _Pragma("unroll")                                                          \
        for (int i = 0; i < 8; i++) {                                              \
            int idx = i * 256 + tid;                                               \
            int n = idx >> 3, k16 = idx & 7;                                       \
            cpasync16(db + n * BSTRIDE + k16 * 16, g_Bh + n * M_ + kt + k16 * 8);  \
        }                                                                          \
        CP_COMMIT();                                                               \
    }

#define STORE_A(buf)                                                               \
    {                                                                              \
        char* sb = sm + (buf) * STAGE;                                             \
        _Pragma("unroll")                                                          \
        for (int i = 0; i < 4; i++) {                                              \
            int idx = i * 256 + tid;                                               \
            int row = idx >> 4, f4 = idx & 15;                                     \
            float4 x = ar[i];                                                      \
            __half h0 = __float2half_rn(x.x), h1 = __float2half_rn(x.y);           \
            __half h2 = __float2half_rn(x.z), h3 = __float2half_rn(x.w);           \
            uint32_t off = (uint32_t)(row * ASTRIDE + f4 * 8);                     \
            *(uint2*)(sb + A_HI + off) = make_uint2(pack2h(h0, h1), pack2h(h2, h3)); \
        }                                                                          \
    }

#define COMPUTE(buf)                                                               \
    {                                                                              \
        const uint32_t sbase = smb + (buf) * STAGE;                                \
        _Pragma("unroll")                                                          \
        for (int ks = 0; ks < 4; ks++) {                                           \
            uint32_t ah[2][4];                                                     \
            _Pragma("unroll")                                                      \
            for (int mt = 0; mt < 2; mt++) {                                       \
                uint32_t aoff = (a_ld_row + mt * 16) * ASTRIDE + ks * 32 + a_ld_koff; \
                ldsm_x4(ah[mt], sbase + A_HI + aoff);                              \
            }                                                                      \
            _Pragma("unroll")                                                      \
            for (int p = 0; p < 4; p++) {                                          \
                uint32_t br[4];                                                    \
                uint32_t boff = (b_ld_n + p * 16) * BSTRIDE + ks * 32 + b_ld_koff; \
                ldsm_x4(br, sbase + B_OFF + boff);                                 \
                _Pragma("unroll")                                                  \
                for (int mt = 0; mt < 2; mt++) {                                   \
                    mma_f16(acc[mt][2 * p],     ah[mt], br[0], br[1]);             \
                    mma_f16(acc[mt][2 * p + 1], ah[mt], br[2], br[3]);             \
                }                                                                  \
            }                                                                      \
        }                                                                          \
    }

    // ---- pipelined main loop ----
    CPASYNC_B(0, 0);
    LOADG_A(0);
    __syncthreads();            // Wc0S/Wc1S ready for C_ACCUM
    C_ACCUM(0);
    STORE_A(0);
    CP_WAIT0();
    __syncthreads();
#pragma unroll 1
    for (int c = 0; c < NCHUNK; c++) {
        const int buf = c & 1;
        if (c + 1 < NCHUNK) {
            CPASYNC_B(c + 1, buf ^ 1);
            LOADG_A(c + 1);
            C_ACCUM(c + 1);
        }
        COMPUTE(buf);
        if (c + 1 < NCHUNK) {
            STORE_A(buf ^ 1);
            CP_WAIT0();
        }
        __syncthreads();
    }

    // ---- C reduce over the 16-lane k-slice groups, write fp32 C ----
#pragma unroll
    for (int i = 0; i < 4; i++) {
#pragma unroll
        for (int o = 1; o < 16; o <<= 1) {
            cc[i][0] += __shfl_xor_sync(~0u, cc[i][0], o);
            cc[i][1] += __shfl_xor_sync(~0u, cc[i][1], o);
        }
    }
    if (c_f4 == 0) {
        int r0 = tid >> 4;     // 0..15
#pragma unroll
        for (int i = 0; i < 4; i++)
            *(float2*)(g_C + (n0 + r0 + 16 * i) * 2) = make_float2(cc[i][0], cc[i][1]);
    }

    // ---- fused epilogue: gate + Wa dot, in-thread (v,u) pairs ----
#pragma unroll
    for (int mt = 0; mt < 2; mt++) {
        float p0 = 0.0f, p1 = 0.0f;
#pragma unroll
        for (int nt = 0; nt < 8; nt++) {
            int j = wn * 32 + nt * 4 + (lane & 3);
            float bvj = bvS[j], buj = buS[j], waj = WaS[j];
            p0 += tanhf(acc[mt][nt][0] + bvj) * sigm(acc[mt][nt][1] + buj) * waj;
            p1 += tanhf(acc[mt][nt][2] + bvj) * sigm(acc[mt][nt][3] + buj) * waj;
        }
        p0 += __shfl_xor_sync(~0u, p0, 1); p0 += __shfl_xor_sync(~0u, p0, 2);
        p1 += __shfl_xor_sync(~0u, p1, 1); p1 += __shfl_xor_sync(~0u, p1, 2);
        if ((lane & 3) == 0) {
            int r = wm * 32 + mt * 16 + (lane >> 2);
            red[r][wn] = p0;
            red[r + 8][wn] = p1;
        }
    }
    __syncthreads();
    if (tid < RM) {
        float s = red[tid][0] + red[tid][1] + red[tid][2] + red[tid][3] + __ldg(ba);
        A_raw[n0 + tid] = s;
    }
}

// ============================================================================
// pool: per bag — softmax over T, then out[b] = sum_t w[t] * C[t]  (+bc)
// grid = 128, block = 512
// ============================================================================
__global__ void __launch_bounds__(512) pool_kernel(
    const float* __restrict__ A_raw, const float* __restrict__ bc,
    float* __restrict__ A_sm, float* __restrict__ out)
{
    __shared__ float red[16], redB[16];
    __shared__ float sh_mx, sh_sum;

    const int tid = threadIdx.x;
    const int b = blockIdx.x;
    const int lane = tid & 31, wid = tid >> 5;

    float a = (tid < T_) ? A_raw[b * T_ + tid] : -1e30f;
    float m = a;
#pragma unroll
    for (int o = 16; o; o >>= 1) m = fmaxf(m, __shfl_xor_sync(~0u, m, o));
    if (lane == 0) red[wid] = m;
    __syncthreads();
    if (tid < 32) {
        float v = (tid < 16) ? red[tid] : -1e30f;
#pragma unroll
        for (int o = 16; o; o >>= 1) v = fmaxf(v, __shfl_xor_sync(~0u, v, o));
        if (tid == 0) sh_mx = v;
    }
    __syncthreads();
    float e = (tid < T_) ? expf(a - sh_mx) : 0.0f;
    float s = e;
#pragma unroll
    for (int o = 16; o; o >>= 1) s += __shfl_xor_sync(~0u, s, o);
    __syncthreads();
    if (lane == 0) red[wid] = s;
    __syncthreads();
    if (tid < 32) {
        float v = (tid < 16) ? red[tid] : 0.0f;
#pragma unroll
        for (int o = 16; o; o >>= 1) v += __shfl_xor_sync(~0u, v, o);
        if (tid == 0) sh_sum = v;
    }
    __syncthreads();

    float wt = 0.0f;
    if (tid < T_) {
        wt = e / sh_sum;
        A_sm[b * T_ + tid] = wt;
    }

    float c0 = 0.0f, c1 = 0.0f;
    if (tid < T_) {
        float2 cv = *(const float2*)(g_C + (b * T_ + tid) * 2);
        c0 = wt * cv.x;
        c1 = wt * cv.y;
    }
#pragma unroll
    for (int o = 16; o; o >>= 1) {
        c0 += __shfl_xor_sync(~0u, c0, o);
        c1 += __shfl_xor_sync(~0u, c1, o);
    }
    __syncthreads();
    if (lane == 0) { red[wid] = c0; redB[wid] = c1; }
    __syncthreads();
    if (tid == 0) {
        float r0 = 0.0f, r1 = 0.0f;
#pragma unroll
        for (int i = 0; i < 16; i++) { r0 += red[i]; r1 += redB[i]; }
        out[b * 2 + 0] = r0 + bc[0];
        out[b * 2 + 1] = r1 + bc[1];
    }
}

// ============================================================================
// Launch. Output layout: [out (B*2) | A_sm (B*T) | A_t raw logits (B*T)]
// ============================================================================
extern "C" void kernel_launch(void* const* d_in, const int* in_sizes, int n_in,
                              void* d_out, int out_size)
{
    const float* H  = (const float*)d_in[0];
    const float* Wv = (const float*)d_in[1];
    const float* bv = (const float*)d_in[2];
    const float* Wu = (const float*)d_in[3];
    const float* bu = (const float*)d_in[4];
    const float* Wa = (const float*)d_in[5];
    const float* ba = (const float*)d_in[6];
    const float* Wc = (const float*)d_in[7];
    const float* bc = (const float*)d_in[8];

    float* out   = (float*)d_out;
    float* A_sm  = out + B_ * 2;
    float* A_raw = A_sm + B_ * T_;

    cudaFuncSetAttribute(gemm_attn_kernel,
                         cudaFuncAttributeMaxDynamicSharedMemorySize, DYN);

    prep_kernel<<<NC, M_>>>(Wv, Wu);
    gemm_attn_kernel<<<NROWS / RM, 256, DYN>>>(H, bv, bu, Wa, ba, Wc, A_raw);
    pool_kernel<<<B_, 512>>>(A_raw, bc, A_sm, out);
}